// round 4
// baseline (speedup 1.0000x reference)
#include <cuda_runtime.h>
#include <cstdint>

#define N_DIM   64
#define C_DIM   64
#define HW_DIM  16384
#define BINS    32
#define TOTAL_ELEMS (N_DIM * C_DIM * HW_DIM)   // 67,108,864
#define TOTAL_V4    (TOTAL_ELEMS / 4)          // 16,777,216

#define MM_GRID   256        // minmax blocks; all co-resident on 148 SMs
#define MM_THREADS 256

// Per-block partial min/max. Every slot is overwritten on every run, so no
// initialization kernel is needed (graph-replay deterministic).
__device__ float g_pmin[MM_GRID];
__device__ float g_pmax[MM_GRID];

// Hardware tanh (MUFU.TANH, sm_75+): single-op, ~2^-11 rel accuracy.
__device__ __forceinline__ float htanh(float x) {
    float y;
    asm("tanh.approx.f32 %0, %1;" : "=f"(y) : "f"(x));
    return y;
}

__global__ void __launch_bounds__(MM_THREADS) minmax_kernel(const float4* __restrict__ x) {
    float vmin =  3.402823466e38f;
    float vmax = -3.402823466e38f;
    // Each block owns a contiguous slab: better DRAM page locality.
    const int per_block = TOTAL_V4 / MM_GRID;          // 65536 float4
    const float4* xb = x + (size_t)blockIdx.x * per_block;
    #pragma unroll 4
    for (int i = threadIdx.x; i < per_block; i += MM_THREADS) {
        float4 v = xb[i];
        vmin = fminf(vmin, fminf(fminf(v.x, v.y), fminf(v.z, v.w)));
        vmax = fmaxf(vmax, fmaxf(fmaxf(v.x, v.y), fmaxf(v.z, v.w)));
    }
    // warp reduce
    #pragma unroll
    for (int off = 16; off > 0; off >>= 1) {
        vmin = fminf(vmin, __shfl_xor_sync(0xFFFFFFFFu, vmin, off));
        vmax = fmaxf(vmax, __shfl_xor_sync(0xFFFFFFFFu, vmax, off));
    }
    __shared__ float smin[8], smax[8];
    int wid  = threadIdx.x >> 5;
    int lane = threadIdx.x & 31;
    if (lane == 0) { smin[wid] = vmin; smax[wid] = vmax; }
    __syncthreads();
    if (threadIdx.x == 0) {
        float bmin = smin[0], bmax = smax[0];
        #pragma unroll
        for (int w = 1; w < 8; w++) {
            bmin = fminf(bmin, smin[w]);
            bmax = fmaxf(bmax, smax[w]);
        }
        g_pmin[blockIdx.x] = bmin;
        g_pmax[blockIdx.x] = bmax;
    }
}

// One block per (n,c) pair: 16384 contiguous floats -> one scalar output.
// z[n,c] = sum_hw tanh(x) * coeff[c, bin(x)]; BINS==32 so the coeff gather
// is a warp shuffle (lane l holds coeff[c][l]).
__global__ void __launch_bounds__(256) hpool_kernel(
    const float* __restrict__ x,
    const float* __restrict__ coeff,
    float* __restrict__ out)
{
    int blk  = blockIdx.x;            // n * C_DIM + c
    int c    = blk & (C_DIM - 1);
    int lane = threadIdx.x & 31;
    int wid  = threadIdx.x >> 5;

    // ---- reduce the 256 partial min/max (L2-resident, hidden under loads) ----
    float vmin = g_pmin[threadIdx.x];
    float vmax = g_pmax[threadIdx.x];
    #pragma unroll
    for (int off = 16; off > 0; off >>= 1) {
        vmin = fminf(vmin, __shfl_xor_sync(0xFFFFFFFFu, vmin, off));
        vmax = fmaxf(vmax, __shfl_xor_sync(0xFFFFFFFFu, vmax, off));
    }
    __shared__ float smm[2][8];
    __shared__ float s_final[2];
    if (lane == 0) { smm[0][wid] = vmin; smm[1][wid] = vmax; }
    __syncthreads();
    if (threadIdx.x == 0) {
        float m0 = smm[0][0], m1 = smm[1][0];
        #pragma unroll
        for (int w = 1; w < 8; w++) {
            m0 = fminf(m0, smm[0][w]);
            m1 = fmaxf(m1, smm[1][w]);
        }
        s_final[0] = m0;
        s_final[1] = m1;
    }
    __syncthreads();
    float xmin  = s_final[0];
    float range = s_final[1] - xmin;
    float scale = (range > 0.f) ? ((float)BINS / range) : 0.f;

    // lane l holds coeff[c][l]; per-element gather is a warp shuffle
    float cw = coeff[c * BINS + lane];

    const float4* xv = (const float4*)(x + (size_t)blk * HW_DIM);
    float acc = 0.f;

    #pragma unroll
    for (int i = 0; i < HW_DIM / (4 * 256); i++) {   // 16 iters
        float4 v = xv[i * 256 + threadIdx.x];
        #pragma unroll
        for (int j = 0; j < 4; j++) {
            float vv = (j == 0) ? v.x : (j == 1) ? v.y : (j == 2) ? v.z : v.w;
            float t = htanh(vv);
            int b = (int)((vv - xmin) * scale);
            b = min(b, BINS - 1);
            float w = __shfl_sync(0xFFFFFFFFu, cw, b);
            acc = fmaf(t, w, acc);
        }
    }

    // block reduce
    #pragma unroll
    for (int off = 16; off > 0; off >>= 1)
        acc += __shfl_xor_sync(0xFFFFFFFFu, acc, off);

    __shared__ float ssum[8];
    if (lane == 0) ssum[wid] = acc;
    __syncthreads();
    if (threadIdx.x == 0) {
        float s = 0.f;
        #pragma unroll
        for (int w = 0; w < 8; w++) s += ssum[w];
        out[blk] = s;
    }
}

extern "C" void kernel_launch(void* const* d_in, const int* in_sizes, int n_in,
                              void* d_out, int out_size) {
    const float* x     = (const float*)d_in[0];
    const float* coeff = (const float*)d_in[1];
    float* out         = (float*)d_out;

    minmax_kernel<<<MM_GRID, MM_THREADS>>>((const float4*)x);
    hpool_kernel<<<N_DIM * C_DIM, 256>>>(x, coeff, out);
}

// round 6
// speedup vs baseline: 1.0437x; 1.0437x over previous
#include <cuda_runtime.h>
#include <cstdint>

#define N_DIM   64
#define C_DIM   64
#define HW_DIM  16384
#define BINS    32
#define TOTAL_ELEMS (N_DIM * C_DIM * HW_DIM)   // 67,108,864
#define TOTAL_V4    (TOTAL_ELEMS / 4)          // 16,777,216

#define MM_GRID    2368      // 148 * 16 — perfectly balanced waves
#define MM_THREADS 256
#define MM_SPAN    (MM_GRID * MM_THREADS)      // 606,208 threads-stride

// Per-block partial min/max. Every slot is overwritten on every run, so no
// initialization kernel is needed (graph-replay deterministic).
__device__ float g_pmin[MM_GRID];
__device__ float g_pmax[MM_GRID];

// Hardware tanh (MUFU.TANH, sm_75+): single-op, ~2^-11 rel accuracy.
__device__ __forceinline__ float htanh(float x) {
    float y;
    asm("tanh.approx.f32 %0, %1;" : "=f"(y) : "f"(x));
    return y;
}

__global__ void __launch_bounds__(MM_THREADS) minmax_kernel(const float4* __restrict__ x) {
    float vmin =  3.402823466e38f;
    float vmax = -3.402823466e38f;

    int tid = blockIdx.x * MM_THREADS + threadIdx.x;
    // TOTAL_V4 / MM_SPAN = 27.68 -> 27 full rounds + ragged tail.
    const int FULL = TOTAL_V4 / MM_SPAN;   // 27
    int r = 0;
    for (; r + 4 <= FULL; r += 4) {
        float4 a = x[tid + (size_t)(r + 0) * MM_SPAN];
        float4 b = x[tid + (size_t)(r + 1) * MM_SPAN];
        float4 c = x[tid + (size_t)(r + 2) * MM_SPAN];
        float4 d = x[tid + (size_t)(r + 3) * MM_SPAN];
        vmin = fminf(vmin, fminf(fminf(a.x, a.y), fminf(a.z, a.w)));
        vmax = fmaxf(vmax, fmaxf(fmaxf(a.x, a.y), fmaxf(a.z, a.w)));
        vmin = fminf(vmin, fminf(fminf(b.x, b.y), fminf(b.z, b.w)));
        vmax = fmaxf(vmax, fmaxf(fmaxf(b.x, b.y), fmaxf(b.z, b.w)));
        vmin = fminf(vmin, fminf(fminf(c.x, c.y), fminf(c.z, c.w)));
        vmax = fmaxf(vmax, fmaxf(fmaxf(c.x, c.y), fmaxf(c.z, c.w)));
        vmin = fminf(vmin, fminf(fminf(d.x, d.y), fminf(d.z, d.w)));
        vmax = fmaxf(vmax, fmaxf(fmaxf(d.x, d.y), fmaxf(d.z, d.w)));
    }
    for (; r < FULL; r++) {
        float4 a = x[tid + (size_t)r * MM_SPAN];
        vmin = fminf(vmin, fminf(fminf(a.x, a.y), fminf(a.z, a.w)));
        vmax = fmaxf(vmax, fmaxf(fmaxf(a.x, a.y), fmaxf(a.z, a.w)));
    }
    // ragged tail
    int idx = tid + FULL * MM_SPAN;
    if (idx < TOTAL_V4) {
        float4 a = x[idx];
        vmin = fminf(vmin, fminf(fminf(a.x, a.y), fminf(a.z, a.w)));
        vmax = fmaxf(vmax, fmaxf(fmaxf(a.x, a.y), fmaxf(a.z, a.w)));
    }

    // warp reduce
    #pragma unroll
    for (int off = 16; off > 0; off >>= 1) {
        vmin = fminf(vmin, __shfl_xor_sync(0xFFFFFFFFu, vmin, off));
        vmax = fmaxf(vmax, __shfl_xor_sync(0xFFFFFFFFu, vmax, off));
    }
    __shared__ float smin[8], smax[8];
    int wid  = threadIdx.x >> 5;
    int lane = threadIdx.x & 31;
    if (lane == 0) { smin[wid] = vmin; smax[wid] = vmax; }
    __syncthreads();
    if (threadIdx.x == 0) {
        float bmin = smin[0], bmax = smax[0];
        #pragma unroll
        for (int w = 1; w < 8; w++) {
            bmin = fminf(bmin, smin[w]);
            bmax = fmaxf(bmax, smax[w]);
        }
        g_pmin[blockIdx.x] = bmin;
        g_pmax[blockIdx.x] = bmax;
    }
}

// One block per (n,c) pair: 16384 contiguous floats -> one scalar output.
// z[n,c] = sum_hw tanh(x) * coeff[c, bin(x)]; BINS==32 so the coeff gather
// is a warp shuffle (lane l holds coeff[c][l]).
__global__ void __launch_bounds__(256, 4) hpool_kernel(
    const float* __restrict__ x,
    const float* __restrict__ coeff,
    float* __restrict__ out)
{
    int blk  = blockIdx.x;            // n * C_DIM + c
    int c    = blk & (C_DIM - 1);
    int lane = threadIdx.x & 31;
    int wid  = threadIdx.x >> 5;

    // ---- reduce the partial min/max (L2-resident) ----
    float vmin =  3.402823466e38f;
    float vmax = -3.402823466e38f;
    #pragma unroll
    for (int i = threadIdx.x; i < MM_GRID; i += 256) {
        vmin = fminf(vmin, g_pmin[i]);
        vmax = fmaxf(vmax, g_pmax[i]);
    }
    #pragma unroll
    for (int off = 16; off > 0; off >>= 1) {
        vmin = fminf(vmin, __shfl_xor_sync(0xFFFFFFFFu, vmin, off));
        vmax = fmaxf(vmax, __shfl_xor_sync(0xFFFFFFFFu, vmax, off));
    }
    __shared__ float smm[2][8];
    __shared__ float s_final[2];
    if (lane == 0) { smm[0][wid] = vmin; smm[1][wid] = vmax; }
    __syncthreads();
    if (threadIdx.x == 0) {
        float m0 = smm[0][0], m1 = smm[1][0];
        #pragma unroll
        for (int w = 1; w < 8; w++) {
            m0 = fminf(m0, smm[0][w]);
            m1 = fmaxf(m1, smm[1][w]);
        }
        s_final[0] = m0;
        s_final[1] = m1;
    }
    __syncthreads();
    float xmin  = s_final[0];
    float range = s_final[1] - xmin;
    float scale = (range > 0.f) ? ((float)BINS / range) : 0.f;

    // lane l holds coeff[c][l]; per-element gather is a warp shuffle
    float cw = coeff[c * BINS + lane];

    const float4* xv = (const float4*)(x + (size_t)blk * HW_DIM);
    float acc = 0.f;

    // 16 float4 per thread, in batches of 4 independent loads (MLP_p1 = 4)
    #pragma unroll
    for (int ii = 0; ii < 4; ii++) {
        float4 v0 = xv[(ii * 4 + 0) * 256 + threadIdx.x];
        float4 v1 = xv[(ii * 4 + 1) * 256 + threadIdx.x];
        float4 v2 = xv[(ii * 4 + 2) * 256 + threadIdx.x];
        float4 v3 = xv[(ii * 4 + 3) * 256 + threadIdx.x];
        float e[16] = { v0.x, v0.y, v0.z, v0.w,
                        v1.x, v1.y, v1.z, v1.w,
                        v2.x, v2.y, v2.z, v2.w,
                        v3.x, v3.y, v3.z, v3.w };
        #pragma unroll
        for (int j = 0; j < 16; j++) {
            float vv = e[j];
            float t = htanh(vv);
            int b = (int)((vv - xmin) * scale);
            b = min(b, BINS - 1);
            float w = __shfl_sync(0xFFFFFFFFu, cw, b);
            acc = fmaf(t, w, acc);
        }
    }

    // block reduce
    #pragma unroll
    for (int off = 16; off > 0; off >>= 1)
        acc += __shfl_xor_sync(0xFFFFFFFFu, acc, off);

    __shared__ float ssum[8];
    if (lane == 0) ssum[wid] = acc;
    __syncthreads();
    if (threadIdx.x == 0) {
        float s = 0.f;
        #pragma unroll
        for (int w = 0; w < 8; w++) s += ssum[w];
        out[blk] = s;
    }
}

extern "C" void kernel_launch(void* const* d_in, const int* in_sizes, int n_in,
                              void* d_out, int out_size) {
    const float* x     = (const float*)d_in[0];
    const float* coeff = (const float*)d_in[1];
    float* out         = (float*)d_out;

    minmax_kernel<<<MM_GRID, MM_THREADS>>>((const float4*)x);
    hpool_kernel<<<N_DIM * C_DIM, 256>>>(x, coeff, out);
}